// round 10
// baseline (speedup 1.0000x reference)
#include <cuda_runtime.h>
#include <math.h>

#define N_NODES 256
#define E_EDGES 320
#define DE      640
#define HV      128
#define MV      128
#define DISD    8
#define ANGD    16
#define CAP     64
#define WATT_LD 416
#define WLNK_LD 264

// ---------------- scratch ----------------
__device__ int   g_U[DE], g_V[DE];
__device__ float g_norm[DE * 3];
__device__ __align__(16) float g_disftr[DE * DISD];
__device__ float g_align[DE];
__device__ float g_c[4 * N_NODES * MV];   // c1,c2,c3,c4 per-node projections
__device__ float g_att[DE * MV];
__device__ float g_attsum[4 * MV];
__device__ float g_wc[ANGD * MV];         // W_att[:,400:416] transposed [k][m]
__device__ float g_sw[N_NODES * CAP];
__device__ int   g_adjU_cnt[N_NODES], g_adjV_cnt[N_NODES];
__device__ int   g_adjU[N_NODES * CAP], g_adjV[N_NODES * CAP];

__device__ __forceinline__ float dot4(float4 a, float4 b) {
    return a.x * b.x + a.y * b.y + a.z * b.z + a.w * b.w;
}

// ============ K1: one-wave fused kernel ======================================
// bid <  64  : node GEMM (4 nodes/block, float4-tiled smem both sides)
// bid <  104 : decode + geometry + disftr + align (8 edges/block)
// bid <  136 : adjacency (8 warps/block, one node per warp, both lists)
// bid == 136 : wc transpose + attsum zero
__global__ void __launch_bounds__(256) k_main(
        const float* __restrict__ hv, const float* __restrict__ he,
        const float* __restrict__ q,
        const float* __restrict__ vew1, const float* __restrict__ vew2,
        const float* __restrict__ W_dis, const float* __restrict__ b_dis,
        const float* __restrict__ W_att,
        const float* __restrict__ W_align, const float* __restrict__ b_align,
        const float* __restrict__ W_link) {
    const int bid = blockIdx.x;
    const int t = threadIdx.x;

    if (bid < 64) {
        // ---- per-node projections c1..c4 ----
        const int n0 = bid * 4;
        const int m = t & 127;
        const int h = t >> 7;                   // 0 -> {c1,c2}, 1 -> {c3,c4}
        __shared__ float4 sX4[4][32];           // [node][k4]
        __shared__ float4 wt4[4][128][5];       // [proj][m][k4], pad -> conflict-free

        if (t < 128) {                          // stage X (broadcast source)
            int nn = t >> 5, kk = t & 31;
            sX4[nn][kk] = *(const float4*)(hv + (n0 + nn) * HV + kk * 4);
        }

        const float* srcs[2];
        int lds[2];
        if (h == 0) { srcs[0] = W_att;       lds[0] = WATT_LD;
                      srcs[1] = W_att + 136; lds[1] = WATT_LD; }
        else        { srcs[0] = W_att + 264; lds[0] = WATT_LD;
                      srcs[1] = W_link;      lds[1] = WLNK_LD; }

        float acc[2][4];
        #pragma unroll
        for (int p = 0; p < 2; p++)
            #pragma unroll
            for (int nn = 0; nn < 4; nn++) acc[p][nn] = 0.0f;

        for (int kt = 0; kt < 8; kt++) {        // 16-k tiles
            __syncthreads();                    // prev tile consumed / sX ready
            #pragma unroll
            for (int p = 0; p < 2; p++) {
                const float* src = srcs[p];
                const int ld = lds[p];
                #pragma unroll
                for (int i = 0; i < 4; i++) {
                    int c = m + 128 * i;        // chunk-linear: coalesced
                    int row = c >> 2, j = c & 3;
                    float4 w = *(const float4*)(src + row * ld + kt * 16 + j * 4);
                    if (h == 1 && p == 1) {     // c4: W_link u-part + v-part
                        float4 w2 = *(const float4*)(src + row * ld + 136 + kt * 16 + j * 4);
                        w.x += w2.x; w.y += w2.y; w.z += w2.z; w.w += w2.w;
                    }
                    wt4[h * 2 + p][row][j] = w;
                }
            }
            __syncthreads();
            #pragma unroll
            for (int g = 0; g < 4; g++) {
                float4 w0 = wt4[h * 2 + 0][m][g];
                float4 w1 = wt4[h * 2 + 1][m][g];
                int kk = kt * 4 + g;
                #pragma unroll
                for (int nn = 0; nn < 4; nn++) {
                    float4 xv = sX4[nn][kk];
                    acc[0][nn] += dot4(xv, w0);
                    acc[1][nn] += dot4(xv, w1);
                }
            }
        }
        #pragma unroll
        for (int p = 0; p < 2; p++)
            #pragma unroll
            for (int nn = 0; nn < 4; nn++)
                g_c[((h * 2 + p) * N_NODES + n0 + nn) * MV + m] = acc[p][nn];
    } else if (bid < 104) {
        // ---- decode 8 edges + align + geometry + disftr ----
        const int e0 = (bid - 64) * 8;
        __shared__ int s_u[8], s_v[8];
        {
            float4 a1l = *(const float4*)(vew1 + t * E_EDGES + e0);
            float4 a1h = *(const float4*)(vew1 + t * E_EDGES + e0 + 4);
            float4 a2l = *(const float4*)(vew2 + t * E_EDGES + e0);
            float4 a2h = *(const float4*)(vew2 + t * E_EDGES + e0 + 4);
            if (a1l.x != 0.0f) s_u[0] = t;
            if (a1l.y != 0.0f) s_u[1] = t;
            if (a1l.z != 0.0f) s_u[2] = t;
            if (a1l.w != 0.0f) s_u[3] = t;
            if (a1h.x != 0.0f) s_u[4] = t;
            if (a1h.y != 0.0f) s_u[5] = t;
            if (a1h.z != 0.0f) s_u[6] = t;
            if (a1h.w != 0.0f) s_u[7] = t;
            if (a2l.x != 0.0f) s_v[0] = t;
            if (a2l.y != 0.0f) s_v[1] = t;
            if (a2l.z != 0.0f) s_v[2] = t;
            if (a2l.w != 0.0f) s_v[3] = t;
            if (a2h.x != 0.0f) s_v[4] = t;
            if (a2h.y != 0.0f) s_v[5] = t;
            if (a2h.z != 0.0f) s_v[6] = t;
            if (a2h.w != 0.0f) s_v[7] = t;
        }
        __syncthreads();
        {   // align: one warp per edge (8 warps)
            int w = t >> 5, lane = t & 31;
            int e = e0 + w;
            float val = 0.0f;
            #pragma unroll
            for (int k = 0; k < 4; k++) {
                int c = lane + 32 * k;
                val += he[e * HV + c] * W_align[c];
            }
            #pragma unroll
            for (int s = 16; s > 0; s >>= 1)
                val += __shfl_down_sync(0xFFFFFFFFu, val, s);
            if (lane == 0) {
                float al = val + b_align[0];
                g_align[e] = al;
                g_align[e + E_EDGES] = al;
            }
        }
        if (t < 64) {                           // geometry + disftr
            int ei = t >> 3, kd = t & 7;
            int e = e0 + ei, u = s_u[ei], v = s_v[ei];
            float qx = q[v * 3 + 0] - q[u * 3 + 0];
            float qy = q[v * 3 + 1] - q[u * 3 + 1];
            float qz = q[v * 3 + 2] - q[u * 3 + 2];
            float dis = sqrtf(qx * qx + qy * qy + qz * qz) + 1e-6f;
            float td = tanhf(dis);
            float dv = tanhf(td * W_dis[kd] + b_dis[kd]);
            g_disftr[e * DISD + kd] = dv;
            g_disftr[(e + E_EDGES) * DISD + kd] = dv;
            if (kd == 0) {
                float inv = 1.0f / dis;
                g_norm[e * 3 + 0] = qx * inv;
                g_norm[e * 3 + 1] = qy * inv;
                g_norm[e * 3 + 2] = qz * inv;
                g_norm[(e + E_EDGES) * 3 + 0] = -qx * inv;
                g_norm[(e + E_EDGES) * 3 + 1] = -qy * inv;
                g_norm[(e + E_EDGES) * 3 + 2] = -qz * inv;
            }
        }
        if (t >= 64 && t < 72) {
            int ei = t - 64, e = e0 + ei;
            g_U[e] = s_u[ei]; g_V[e] = s_v[ei];
            g_U[e + E_EDGES] = s_v[ei]; g_V[e + E_EDGES] = s_u[ei];
        }
    } else if (bid < 136) {
        // ---- adjacency: one warp per node, BOTH lists (interleaved latency) ----
        int lane = t & 31;
        int n = (bid - 104) * 8 + (t >> 5);
        unsigned lml = (1u << lane) - 1u;
        int cu = 0, cv = 0;
        int* lu = g_adjU + n * CAP;
        int* lv = g_adjV + n * CAP;
        #pragma unroll
        for (int pass = 0; pass < 2; pass++) {
            const float* rU = pass ? vew2 : vew1;   // contributes to adjU
            const float* rV = pass ? vew1 : vew2;   // contributes to adjV
            int dofs = pass ? E_EDGES : 0;
            #pragma unroll
            for (int e0 = 0; e0 < E_EDGES; e0 += 128) {
                int e = e0 + 4 * lane;
                float4 xu = make_float4(0.f, 0.f, 0.f, 0.f);
                float4 xv = make_float4(0.f, 0.f, 0.f, 0.f);
                if (e < E_EDGES) {
                    xu = *(const float4*)(rU + n * E_EDGES + e);
                    xv = *(const float4*)(rV + n * E_EDGES + e);
                }
                int u0 = (xu.x != 0.f), u1 = (xu.y != 0.f), u2 = (xu.z != 0.f), u3 = (xu.w != 0.f);
                int v0 = (xv.x != 0.f), v1 = (xv.y != 0.f), v2 = (xv.z != 0.f), v3 = (xv.w != 0.f);
                int lcU = u0 + u1 + u2 + u3, lcV = v0 + v1 + v2 + v3;
                int incU = lcU, incV = lcV;
                #pragma unroll
                for (int s = 1; s < 32; s <<= 1) {
                    int a = __shfl_up_sync(0xFFFFFFFFu, incU, s);
                    int b = __shfl_up_sync(0xFFFFFFFFu, incV, s);
                    if (lane >= s) { incU += a; incV += b; }
                }
                int offU = cu + incU - lcU, offV = cv + incV - lcV;
                if (u0) lu[offU++] = e + 0 + dofs;
                if (u1) lu[offU++] = e + 1 + dofs;
                if (u2) lu[offU++] = e + 2 + dofs;
                if (u3) lu[offU++] = e + 3 + dofs;
                if (v0) lv[offV++] = e + 0 + dofs;
                if (v1) lv[offV++] = e + 1 + dofs;
                if (v2) lv[offV++] = e + 2 + dofs;
                if (v3) lv[offV++] = e + 3 + dofs;
                cu += __shfl_sync(0xFFFFFFFFu, incU, 31);
                cv += __shfl_sync(0xFFFFFFFFu, incV, 31);
            }
        }
        if (lane == 0) { g_adjU_cnt[n] = cu; g_adjV_cnt[n] = cv; }
    } else {
        for (int j = t; j < 4 * MV; j += 256) g_attsum[j] = 0.0f;
        for (int j = t; j < ANGD * MV; j += 256) {
            int k = j >> 7, mm = j & 127;
            g_wc[j] = W_att[mm * WATT_LD + 400 + k];
        }
    }
}

// ============ K2: attend (inline a/b) + me combine + node softmax ============
__global__ void __launch_bounds__(256) k_mid(
        const float* __restrict__ W_ang, const float* __restrict__ b_ang,
        const float* __restrict__ W_att, const float* __restrict__ W_link,
        const float* __restrict__ b_link, float* __restrict__ out) {
    const int t = threadIdx.x;
    const int lane = t & 31;
    const int gw = blockIdx.x * 8 + (t >> 5);

    if (gw < DE * 4) {
        // ---- attend: warp task (directed edge i, column quarter) ----
        int i = gw >> 2;
        int m = (gw & 3) * 32 + lane;
        const float4* wr = (const float4*)(W_att + m * WATT_LD);
        float4 wda0 = wr[32], wda1 = wr[33];        // A: dis cols
        float4 wdb0 = wr[98], wdb1 = wr[99];        // b: dis cols
        float wang = 0.f, bang = 0.f;
        if (lane < ANGD) { wang = W_ang[lane]; bang = b_ang[lane]; }
        float wc[ANGD];
        #pragma unroll
        for (int k = 0; k < ANGD; k++) wc[k] = g_wc[k * MV + m];

        float4 d0 = *(const float4*)(g_disftr + i * DISD);
        float4 d1 = *(const float4*)(g_disftr + i * DISD + 4);
        float ai = g_c[(0 * N_NODES + g_V[i]) * MV + m]
                 + g_c[(1 * N_NODES + g_U[i]) * MV + m]
                 + dot4(d0, wda0) + dot4(d1, wda1);
        float nix = g_norm[i * 3 + 0], niy = g_norm[i * 3 + 1], niz = g_norm[i * 3 + 2];
        int u = g_U[i];
        int cnt = g_adjU_cnt[u];
        float amax = 0.0f;                     // relu floor
        for (int idx = 0; idx < cnt; idx++) {
            int j = g_adjU[u * CAP + idx];
            float4 e0 = *(const float4*)(g_disftr + j * DISD);
            float4 e1 = *(const float4*)(g_disftr + j * DISD + 4);
            float bj = g_c[(2 * N_NODES + g_V[j]) * MV + m]
                     + dot4(e0, wdb0) + dot4(e1, wdb1);
            float ang = nix * g_norm[j * 3 + 0] + niy * g_norm[j * 3 + 1]
                      + niz * g_norm[j * 3 + 2];
            float sh = 0.0f;
            if (lane < ANGD) sh = tanhf(ang * wang + bang);
            float c = 0.0f;
            #pragma unroll
            for (int k = 0; k < ANGD; k++)
                c += __shfl_sync(0xFFFFFFFFu, sh, k) * wc[k];
            amax = fmaxf(amax, ai + bj + c);
        }
        g_att[i * MV + m] = amax;
        atomicAdd(&g_attsum[(i & 3) * MV + m], amax);
    } else if (gw < DE * 4 + E_EDGES * 4) {
        // ---- me combine: warp task (edge e, column quarter) ----
        int task = gw - DE * 4;
        int e = task >> 2;
        int m = (task & 3) * 32 + lane;
        const float4* lr = (const float4*)(W_link + m * WLNK_LD);
        float4 wdm0 = lr[32], wdm1 = lr[33];
        float4 d0 = *(const float4*)(g_disftr + e * DISD);
        float4 d1 = *(const float4*)(g_disftr + e * DISD + 4);
        float x = g_c[(3 * N_NODES + g_U[e]) * MV + m]
                + g_c[(3 * N_NODES + g_V[e]) * MV + m]
                + 2.0f * (dot4(d0, wdm0) + dot4(d1, wdm1) + b_link[m]);
        out[N_NODES * MV + e * MV + m] = (x >= 0.0f) ? x : 0.01f * x;
    } else if (gw < DE * 4 + E_EDGES * 4 + N_NODES) {
        // ---- node softmax weights: one warp per node ----
        int n = gw - DE * 4 - E_EDGES * 4;
        int cnt = g_adjV_cnt[n];
        if (cnt == 0) return;
        if (cnt <= 32) {
            float a = (lane < cnt) ? g_align[g_adjV[n * CAP + lane]] : -1e30f;
            float mx = a;
            #pragma unroll
            for (int s = 16; s > 0; s >>= 1)
                mx = fmaxf(mx, __shfl_xor_sync(0xFFFFFFFFu, mx, s));
            float w = (lane < cnt) ? expf(a - mx) : 0.0f;
            float den = w;
            #pragma unroll
            for (int s = 16; s > 0; s >>= 1)
                den += __shfl_xor_sync(0xFFFFFFFFu, den, s);
            if (lane < cnt) g_sw[n * CAP + lane] = w / den;
        } else if (lane == 0) {                // safety fallback
            float mx = -1e30f;
            for (int idx = 0; idx < cnt; idx++)
                mx = fmaxf(mx, g_align[g_adjV[n * CAP + idx]]);
            float den = 0.0f;
            for (int idx = 0; idx < cnt; idx++)
                den += expf(g_align[g_adjV[n * CAP + idx]] - mx);
            for (int idx = 0; idx < cnt; idx++)
                g_sw[n * CAP + idx] = expf(g_align[g_adjV[n * CAP + idx]] - mx) / den;
        }
    }
}

// ============ K3: weighted gather + elu -> mv ================================
__global__ void __launch_bounds__(128) k_mv(float* __restrict__ out) {
    int n = blockIdx.x;
    int t = threadIdx.x;
    int cnt = g_adjV_cnt[n];
    float r;
    if (cnt == 0) {
        r = (g_attsum[t] + g_attsum[MV + t] + g_attsum[2 * MV + t]
             + g_attsum[3 * MV + t]) * (1.0f / (float)DE);
    } else {
        float acc = 0.0f;
        int idx = 0;
        for (; idx + 2 <= cnt; idx += 2) {
            int d0 = g_adjV[n * CAP + idx];
            int d1 = g_adjV[n * CAP + idx + 1];
            float w0 = g_sw[n * CAP + idx];
            float w1 = g_sw[n * CAP + idx + 1];
            acc += w0 * g_att[d0 * MV + t] + w1 * g_att[d1 * MV + t];
        }
        if (idx < cnt)
            acc += g_sw[n * CAP + idx] * g_att[g_adjV[n * CAP + idx] * MV + t];
        r = acc;
    }
    out[n * MV + t] = (r > 0.0f) ? r : expm1f(r);
}

// ---------------- launch ----------------
extern "C" void kernel_launch(void* const* d_in, const int* in_sizes, int n_in,
                              void* d_out, int out_size) {
    const float* hv      = (const float*)d_in[0];
    const float* he      = (const float*)d_in[1];
    const float* q       = (const float*)d_in[3];
    const float* vew1    = (const float*)d_in[4];
    const float* vew2    = (const float*)d_in[5];
    const float* W_dis   = (const float*)d_in[8];
    const float* b_dis   = (const float*)d_in[9];
    const float* W_ang   = (const float*)d_in[10];
    const float* b_ang   = (const float*)d_in[11];
    const float* W_att   = (const float*)d_in[12];
    const float* W_align = (const float*)d_in[13];
    const float* b_align = (const float*)d_in[14];
    const float* W_link  = (const float*)d_in[15];
    const float* b_link  = (const float*)d_in[16];
    float* out = (float*)d_out;

    k_main<<<137, 256>>>(hv, he, q, vew1, vew2, W_dis, b_dis, W_att,
                         W_align, b_align, W_link);
    k_mid<<<(DE * 4 + E_EDGES * 4 + N_NODES + 7) / 8, 256>>>(
        W_ang, b_ang, W_att, W_link, b_link, out);
    k_mv<<<N_NODES, 128>>>(out);
}

// round 11
// speedup vs baseline: 1.0954x; 1.0954x over previous
#include <cuda_runtime.h>
#include <math.h>

#define N_NODES 256
#define E_EDGES 320
#define DE      640
#define HV      128
#define MV      128
#define DISD    8
#define ANGD    16
#define CAP     64
#define WATT_LD 416
#define WLNK_LD 264

// dynamic smem: weight tile [4 proj][128 m][17 float4 (16 used + pad)]
#define WT_STRIDE_M   17
#define WT_STRIDE_P   (128 * WT_STRIDE_M)
#define DYN_SMEM_BYTES (4 * WT_STRIDE_P * 16)

// ---------------- scratch ----------------
__device__ int   g_U[DE], g_V[DE];
__device__ float g_norm[DE * 3];
__device__ __align__(16) float g_disftr[DE * DISD];
__device__ float g_align[DE];
__device__ float g_c[4 * N_NODES * MV];   // c1,c2,c3,c4 per-node projections
__device__ float g_att[DE * MV];
__device__ float g_attsum[4 * MV];
__device__ float g_wc[ANGD * MV];         // W_att[:,400:416] transposed [k][m]
__device__ float g_sw[N_NODES * CAP];
__device__ int   g_adjU_cnt[N_NODES], g_adjV_cnt[N_NODES];
__device__ int   g_adjU[N_NODES * CAP], g_adjV[N_NODES * CAP];

__device__ __forceinline__ float dot4(float4 a, float4 b) {
    return a.x * b.x + a.y * b.y + a.z * b.z + a.w * b.w;
}

// ============ K1: one-wave fused kernel ======================================
// bid <  64  : node GEMM (4 nodes/block; 2 big k-tiles, MLP=32 weight staging)
// bid <  104 : decode + geometry + disftr + align (8 edges/block)
// bid <  136 : adjacency (8 warps/block, one node per warp, both lists)
// bid == 136 : wc transpose + attsum zero
__global__ void __launch_bounds__(256) k_main(
        const float* __restrict__ hv, const float* __restrict__ he,
        const float* __restrict__ q,
        const float* __restrict__ vew1, const float* __restrict__ vew2,
        const float* __restrict__ W_dis, const float* __restrict__ b_dis,
        const float* __restrict__ W_att,
        const float* __restrict__ W_align, const float* __restrict__ b_align,
        const float* __restrict__ W_link) {
    extern __shared__ float4 wt[];          // [4][128][17]
    const int bid = blockIdx.x;
    const int t = threadIdx.x;

    if (bid < 64) {
        // ---- per-node projections c1..c4 ----
        const int n0 = bid * 4;
        const int m = t & 127;
        const int h = t >> 7;               // 0 -> {c1,c2}, 1 -> {c3,c4}
        __shared__ float4 sX4[4][32];       // [node][k4]

        if (t < 128) {                      // stage X (broadcast source)
            int nn = t >> 5, kk = t & 31;
            sX4[nn][kk] = *(const float4*)(hv + (n0 + nn) * HV + kk * 4);
        }

        float acc[2][4];
        #pragma unroll
        for (int p = 0; p < 2; p++)
            #pragma unroll
            for (int nn = 0; nn < 4; nn++) acc[p][nn] = 0.0f;

        #pragma unroll
        for (int kt = 0; kt < 2; kt++) {    // two 64-wide k tiles
            if (kt) __syncthreads();        // prev tile consumed
            // stage: 32 independent coalesced LDG.128 per thread
            #pragma unroll
            for (int i = 0; i < 32; i++) {
                int c = t + 256 * i;        // proj uniform per i (c>>11)
                int proj = c >> 11;
                int mm = (c >> 4) & 127;
                int j = c & 15;
                int k = kt * 64 + j * 4;
                float4 w;
                if (proj == 0)      w = *(const float4*)(W_att + mm * WATT_LD + k);
                else if (proj == 1) w = *(const float4*)(W_att + mm * WATT_LD + 136 + k);
                else if (proj == 2) w = *(const float4*)(W_att + mm * WATT_LD + 264 + k);
                else {
                    w = *(const float4*)(W_link + mm * WLNK_LD + k);
                    float4 w2 = *(const float4*)(W_link + mm * WLNK_LD + 136 + k);
                    w.x += w2.x; w.y += w2.y; w.z += w2.z; w.w += w2.w;
                }
                wt[proj * WT_STRIDE_P + mm * WT_STRIDE_M + j] = w;
            }
            __syncthreads();
            // compute: long burst, no memory latency on critical path
            const float4* w0p = wt + (h * 2 + 0) * WT_STRIDE_P + m * WT_STRIDE_M;
            const float4* w1p = wt + (h * 2 + 1) * WT_STRIDE_P + m * WT_STRIDE_M;
            #pragma unroll
            for (int j4 = 0; j4 < 16; j4++) {
                float4 w0 = w0p[j4];
                float4 w1 = w1p[j4];
                int kk = kt * 16 + j4;
                #pragma unroll
                for (int nn = 0; nn < 4; nn++) {
                    float4 xv = sX4[nn][kk];
                    acc[0][nn] += dot4(xv, w0);
                    acc[1][nn] += dot4(xv, w1);
                }
            }
        }
        #pragma unroll
        for (int p = 0; p < 2; p++)
            #pragma unroll
            for (int nn = 0; nn < 4; nn++)
                g_c[((h * 2 + p) * N_NODES + n0 + nn) * MV + m] = acc[p][nn];
    } else if (bid < 104) {
        // ---- decode 8 edges + align + geometry + disftr ----
        const int e0 = (bid - 64) * 8;
        __shared__ int s_u[8], s_v[8];
        {
            float4 a1l = *(const float4*)(vew1 + t * E_EDGES + e0);
            float4 a1h = *(const float4*)(vew1 + t * E_EDGES + e0 + 4);
            float4 a2l = *(const float4*)(vew2 + t * E_EDGES + e0);
            float4 a2h = *(const float4*)(vew2 + t * E_EDGES + e0 + 4);
            if (a1l.x != 0.0f) s_u[0] = t;
            if (a1l.y != 0.0f) s_u[1] = t;
            if (a1l.z != 0.0f) s_u[2] = t;
            if (a1l.w != 0.0f) s_u[3] = t;
            if (a1h.x != 0.0f) s_u[4] = t;
            if (a1h.y != 0.0f) s_u[5] = t;
            if (a1h.z != 0.0f) s_u[6] = t;
            if (a1h.w != 0.0f) s_u[7] = t;
            if (a2l.x != 0.0f) s_v[0] = t;
            if (a2l.y != 0.0f) s_v[1] = t;
            if (a2l.z != 0.0f) s_v[2] = t;
            if (a2l.w != 0.0f) s_v[3] = t;
            if (a2h.x != 0.0f) s_v[4] = t;
            if (a2h.y != 0.0f) s_v[5] = t;
            if (a2h.z != 0.0f) s_v[6] = t;
            if (a2h.w != 0.0f) s_v[7] = t;
        }
        __syncthreads();
        {   // align: one warp per edge (8 warps)
            int w = t >> 5, lane = t & 31;
            int e = e0 + w;
            float val = 0.0f;
            #pragma unroll
            for (int k = 0; k < 4; k++) {
                int c = lane + 32 * k;
                val += he[e * HV + c] * W_align[c];
            }
            #pragma unroll
            for (int s = 16; s > 0; s >>= 1)
                val += __shfl_down_sync(0xFFFFFFFFu, val, s);
            if (lane == 0) {
                float al = val + b_align[0];
                g_align[e] = al;
                g_align[e + E_EDGES] = al;
            }
        }
        if (t < 64) {                       // geometry + disftr
            int ei = t >> 3, kd = t & 7;
            int e = e0 + ei, u = s_u[ei], v = s_v[ei];
            float qx = q[v * 3 + 0] - q[u * 3 + 0];
            float qy = q[v * 3 + 1] - q[u * 3 + 1];
            float qz = q[v * 3 + 2] - q[u * 3 + 2];
            float dis = sqrtf(qx * qx + qy * qy + qz * qz) + 1e-6f;
            float td = tanhf(dis);
            float dv = tanhf(td * W_dis[kd] + b_dis[kd]);
            g_disftr[e * DISD + kd] = dv;
            g_disftr[(e + E_EDGES) * DISD + kd] = dv;
            if (kd == 0) {
                float inv = 1.0f / dis;
                g_norm[e * 3 + 0] = qx * inv;
                g_norm[e * 3 + 1] = qy * inv;
                g_norm[e * 3 + 2] = qz * inv;
                g_norm[(e + E_EDGES) * 3 + 0] = -qx * inv;
                g_norm[(e + E_EDGES) * 3 + 1] = -qy * inv;
                g_norm[(e + E_EDGES) * 3 + 2] = -qz * inv;
            }
        }
        if (t >= 64 && t < 72) {
            int ei = t - 64, e = e0 + ei;
            g_U[e] = s_u[ei]; g_V[e] = s_v[ei];
            g_U[e + E_EDGES] = s_v[ei]; g_V[e + E_EDGES] = s_u[ei];
        }
    } else if (bid < 136) {
        // ---- adjacency: one warp per node, BOTH lists (interleaved latency) ----
        int lane = t & 31;
        int n = (bid - 104) * 8 + (t >> 5);
        int cu = 0, cv = 0;
        int* lu = g_adjU + n * CAP;
        int* lv = g_adjV + n * CAP;
        #pragma unroll
        for (int pass = 0; pass < 2; pass++) {
            const float* rU = pass ? vew2 : vew1;   // contributes to adjU
            const float* rV = pass ? vew1 : vew2;   // contributes to adjV
            int dofs = pass ? E_EDGES : 0;
            #pragma unroll
            for (int e0 = 0; e0 < E_EDGES; e0 += 128) {
                int e = e0 + 4 * lane;
                float4 xu = make_float4(0.f, 0.f, 0.f, 0.f);
                float4 xv = make_float4(0.f, 0.f, 0.f, 0.f);
                if (e < E_EDGES) {
                    xu = *(const float4*)(rU + n * E_EDGES + e);
                    xv = *(const float4*)(rV + n * E_EDGES + e);
                }
                int u0 = (xu.x != 0.f), u1 = (xu.y != 0.f), u2 = (xu.z != 0.f), u3 = (xu.w != 0.f);
                int v0 = (xv.x != 0.f), v1 = (xv.y != 0.f), v2 = (xv.z != 0.f), v3 = (xv.w != 0.f);
                int lcU = u0 + u1 + u2 + u3, lcV = v0 + v1 + v2 + v3;
                int incU = lcU, incV = lcV;
                #pragma unroll
                for (int s = 1; s < 32; s <<= 1) {
                    int a = __shfl_up_sync(0xFFFFFFFFu, incU, s);
                    int b = __shfl_up_sync(0xFFFFFFFFu, incV, s);
                    if (lane >= s) { incU += a; incV += b; }
                }
                int offU = cu + incU - lcU, offV = cv + incV - lcV;
                if (u0) lu[offU++] = e + 0 + dofs;
                if (u1) lu[offU++] = e + 1 + dofs;
                if (u2) lu[offU++] = e + 2 + dofs;
                if (u3) lu[offU++] = e + 3 + dofs;
                if (v0) lv[offV++] = e + 0 + dofs;
                if (v1) lv[offV++] = e + 1 + dofs;
                if (v2) lv[offV++] = e + 2 + dofs;
                if (v3) lv[offV++] = e + 3 + dofs;
                cu += __shfl_sync(0xFFFFFFFFu, incU, 31);
                cv += __shfl_sync(0xFFFFFFFFu, incV, 31);
            }
        }
        if (lane == 0) { g_adjU_cnt[n] = cu; g_adjV_cnt[n] = cv; }
    } else {
        for (int j = t; j < 4 * MV; j += 256) g_attsum[j] = 0.0f;
        for (int j = t; j < ANGD * MV; j += 256) {
            int k = j >> 7, mm = j & 127;
            g_wc[j] = W_att[mm * WATT_LD + 400 + k];
        }
    }
}

// ============ K2: attend (inline a/b) + me combine + node softmax ============
__global__ void __launch_bounds__(256) k_mid(
        const float* __restrict__ W_ang, const float* __restrict__ b_ang,
        const float* __restrict__ W_att, const float* __restrict__ W_link,
        const float* __restrict__ b_link, float* __restrict__ out) {
    const int t = threadIdx.x;
    const int lane = t & 31;
    const int gw = blockIdx.x * 8 + (t >> 5);

    if (gw < DE * 4) {
        // ---- attend: warp task (directed edge i, column quarter) ----
        int i = gw >> 2;
        int m = (gw & 3) * 32 + lane;
        const float4* wr = (const float4*)(W_att + m * WATT_LD);
        float4 wda0 = wr[32], wda1 = wr[33];        // A: dis cols
        float4 wdb0 = wr[98], wdb1 = wr[99];        // b: dis cols
        float wang = 0.f, bang = 0.f;
        if (lane < ANGD) { wang = W_ang[lane]; bang = b_ang[lane]; }
        float wc[ANGD];
        #pragma unroll
        for (int k = 0; k < ANGD; k++) wc[k] = g_wc[k * MV + m];

        float4 d0 = *(const float4*)(g_disftr + i * DISD);
        float4 d1 = *(const float4*)(g_disftr + i * DISD + 4);
        float ai = g_c[(0 * N_NODES + g_V[i]) * MV + m]
                 + g_c[(1 * N_NODES + g_U[i]) * MV + m]
                 + dot4(d0, wda0) + dot4(d1, wda1);
        float nix = g_norm[i * 3 + 0], niy = g_norm[i * 3 + 1], niz = g_norm[i * 3 + 2];
        int u = g_U[i];
        int cnt = g_adjU_cnt[u];
        float amax = 0.0f;                     // relu floor
        for (int idx = 0; idx < cnt; idx++) {
            int j = g_adjU[u * CAP + idx];
            float4 e0 = *(const float4*)(g_disftr + j * DISD);
            float4 e1 = *(const float4*)(g_disftr + j * DISD + 4);
            float bj = g_c[(2 * N_NODES + g_V[j]) * MV + m]
                     + dot4(e0, wdb0) + dot4(e1, wdb1);
            float ang = nix * g_norm[j * 3 + 0] + niy * g_norm[j * 3 + 1]
                      + niz * g_norm[j * 3 + 2];
            float sh = 0.0f;
            if (lane < ANGD) sh = tanhf(ang * wang + bang);
            float c = 0.0f;
            #pragma unroll
            for (int k = 0; k < ANGD; k++)
                c += __shfl_sync(0xFFFFFFFFu, sh, k) * wc[k];
            amax = fmaxf(amax, ai + bj + c);
        }
        g_att[i * MV + m] = amax;
        atomicAdd(&g_attsum[(i & 3) * MV + m], amax);
    } else if (gw < DE * 4 + E_EDGES * 4) {
        // ---- me combine: warp task (edge e, column quarter) ----
        int task = gw - DE * 4;
        int e = task >> 2;
        int m = (task & 3) * 32 + lane;
        const float4* lr = (const float4*)(W_link + m * WLNK_LD);
        float4 wdm0 = lr[32], wdm1 = lr[33];
        float4 d0 = *(const float4*)(g_disftr + e * DISD);
        float4 d1 = *(const float4*)(g_disftr + e * DISD + 4);
        float x = g_c[(3 * N_NODES + g_U[e]) * MV + m]
                + g_c[(3 * N_NODES + g_V[e]) * MV + m]
                + 2.0f * (dot4(d0, wdm0) + dot4(d1, wdm1) + b_link[m]);
        out[N_NODES * MV + e * MV + m] = (x >= 0.0f) ? x : 0.01f * x;
    } else if (gw < DE * 4 + E_EDGES * 4 + N_NODES) {
        // ---- node softmax weights: one warp per node ----
        int n = gw - DE * 4 - E_EDGES * 4;
        int cnt = g_adjV_cnt[n];
        if (cnt == 0) return;
        if (cnt <= 32) {
            float a = (lane < cnt) ? g_align[g_adjV[n * CAP + lane]] : -1e30f;
            float mx = a;
            #pragma unroll
            for (int s = 16; s > 0; s >>= 1)
                mx = fmaxf(mx, __shfl_xor_sync(0xFFFFFFFFu, mx, s));
            float w = (lane < cnt) ? expf(a - mx) : 0.0f;
            float den = w;
            #pragma unroll
            for (int s = 16; s > 0; s >>= 1)
                den += __shfl_xor_sync(0xFFFFFFFFu, den, s);
            if (lane < cnt) g_sw[n * CAP + lane] = w / den;
        } else if (lane == 0) {                // safety fallback
            float mx = -1e30f;
            for (int idx = 0; idx < cnt; idx++)
                mx = fmaxf(mx, g_align[g_adjV[n * CAP + idx]]);
            float den = 0.0f;
            for (int idx = 0; idx < cnt; idx++)
                den += expf(g_align[g_adjV[n * CAP + idx]] - mx);
            for (int idx = 0; idx < cnt; idx++)
                g_sw[n * CAP + idx] = expf(g_align[g_adjV[n * CAP + idx]] - mx) / den;
        }
    }
}

// ============ K3: weighted gather + elu -> mv ================================
__global__ void __launch_bounds__(128) k_mv(float* __restrict__ out) {
    int n = blockIdx.x;
    int t = threadIdx.x;
    int cnt = g_adjV_cnt[n];
    float r;
    if (cnt == 0) {
        r = (g_attsum[t] + g_attsum[MV + t] + g_attsum[2 * MV + t]
             + g_attsum[3 * MV + t]) * (1.0f / (float)DE);
    } else {
        float acc = 0.0f;
        int idx = 0;
        for (; idx + 2 <= cnt; idx += 2) {
            int d0 = g_adjV[n * CAP + idx];
            int d1 = g_adjV[n * CAP + idx + 1];
            float w0 = g_sw[n * CAP + idx];
            float w1 = g_sw[n * CAP + idx + 1];
            acc += w0 * g_att[d0 * MV + t] + w1 * g_att[d1 * MV + t];
        }
        if (idx < cnt)
            acc += g_sw[n * CAP + idx] * g_att[g_adjV[n * CAP + idx] * MV + t];
        r = acc;
    }
    out[n * MV + t] = (r > 0.0f) ? r : expm1f(r);
}

// ---------------- launch ----------------
extern "C" void kernel_launch(void* const* d_in, const int* in_sizes, int n_in,
                              void* d_out, int out_size) {
    const float* hv      = (const float*)d_in[0];
    const float* he      = (const float*)d_in[1];
    const float* q       = (const float*)d_in[3];
    const float* vew1    = (const float*)d_in[4];
    const float* vew2    = (const float*)d_in[5];
    const float* W_dis   = (const float*)d_in[8];
    const float* b_dis   = (const float*)d_in[9];
    const float* W_ang   = (const float*)d_in[10];
    const float* b_ang   = (const float*)d_in[11];
    const float* W_att   = (const float*)d_in[12];
    const float* W_align = (const float*)d_in[13];
    const float* b_align = (const float*)d_in[14];
    const float* W_link  = (const float*)d_in[15];
    const float* b_link  = (const float*)d_in[16];
    float* out = (float*)d_out;

    cudaFuncSetAttribute(k_main, cudaFuncAttributeMaxDynamicSharedMemorySize,
                         DYN_SMEM_BYTES);
    k_main<<<137, 256, DYN_SMEM_BYTES>>>(hv, he, q, vew1, vew2, W_dis, b_dis,
                                         W_att, W_align, b_align, W_link);
    k_mid<<<(DE * 4 + E_EDGES * 4 + N_NODES + 7) / 8, 256>>>(
        W_ang, b_ang, W_att, W_link, b_link, out);
    k_mv<<<N_NODES, 128>>>(out);
}